// round 6
// baseline (speedup 1.0000x reference)
#include <cuda_runtime.h>
#include <cstdint>

#define BATCH 32
#define NPTS  2048
#define DIM   16
#define TN    64
#define TM    128
#define NTHR  128
#define ASTR  72             // A transposed row stride (floats), 16B-aligned
#define BSTR  144            // B transposed row stride (floats), gapped
#define BIG2  1.0e16f
#define HUGEV 1.0e30f

typedef unsigned long long ull;

// physical column for Bs_t: 4-float gap every 32 columns (bank de-conflict)
__device__ __forceinline__ int bpcol(int col) { return col + ((col >> 5) << 2); }

// ---------------- scratch (no allocs allowed) ----------------
__device__ float g_cA[BATCH * NPTS * DIM];
__device__ float g_cB[BATCH * NPTS * DIM];
__device__ float g_wA[BATCH * NPTS];
__device__ float g_wB[BATCH * NPTS];
__device__ int   g_cntA[BATCH];
__device__ int   g_cntB[BATCH];
__device__ int   g_colmin[BATCH * NPTS];   // float-as-int (nonneg), +inf init
__device__ int   g_done[BATCH];

// ---------------- packed f32x2 helpers ----------------
__device__ __forceinline__ void fma2(ull& d, ull a, ull b) {
    asm("fma.rn.f32x2 %0, %1, %2, %0;" : "+l"(d) : "l"(a), "l"(b));
}
__device__ __forceinline__ ull fma2v(ull a, ull b, ull c) {
    ull d; asm("fma.rn.f32x2 %0, %1, %2, %3;" : "=l"(d) : "l"(a), "l"(b), "l"(c));
    return d;
}
__device__ __forceinline__ ull add2(ull a, ull b) {
    ull d; asm("add.rn.f32x2 %0, %1, %2;" : "=l"(d) : "l"(a), "l"(b));
    return d;
}
__device__ __forceinline__ ull bcast2(float x) {
    ull d; asm("mov.b64 %0, {%1, %1};" : "=l"(d) : "f"(x));
    return d;
}
__device__ __forceinline__ void unpack2(ull v, float& lo, float& hi) {
    asm("mov.b64 {%0, %1}, %2;" : "=f"(lo), "=f"(hi) : "l"(v));
}

// ---------------- setup: init + prefix-scan compaction ----------------
__global__ __launch_bounds__(256) void setup_kernel(
    const float* __restrict__ ow, const float* __restrict__ op,
    const float* __restrict__ tw, const float* __restrict__ tp,
    float* out) {
    int blk = blockIdx.x;              // 64 blocks: (b, sel)
    int b   = blk >> 1;
    int sel = blk & 1;
    int tid = threadIdx.x, lane = tid & 31, wrp = tid >> 5;

    int base = blk * 1024;
    for (int i = tid; i < 1024; i += 256) g_colmin[base + i] = 0x7F800000;
    if (sel == 0 && tid == 0) { out[b] = 0.0f; g_done[b] = 0; }

    const float* w   = sel ? tw : ow;
    const float* pts = sel ? tp : op;
    float* dstP = sel ? g_cB : g_cA;
    float* dstW = sel ? g_wB : g_wA;
    int*   cnt  = sel ? g_cntB : g_cntA;

    int i0 = tid * 8;
    float wv[8];
    int c = 0;
    #pragma unroll
    for (int k = 0; k < 8; k++) {
        wv[k] = w[b * NPTS + i0 + k];
        c += (wv[k] != 0.0f);
    }
    int incl = c;
    #pragma unroll
    for (int d = 1; d < 32; d <<= 1) {
        int n = __shfl_up_sync(0xFFFFFFFFu, incl, d);
        if (lane >= d) incl += n;
    }
    __shared__ int wtot[8], wbase[8];
    if (lane == 31) wtot[wrp] = incl;
    __syncthreads();
    if (tid == 0) {
        int s = 0;
        #pragma unroll
        for (int wI = 0; wI < 8; wI++) { wbase[wI] = s; s += wtot[wI]; }
        cnt[b] = s;
    }
    __syncthreads();
    int p = wbase[wrp] + incl - c;
    #pragma unroll
    for (int k = 0; k < 8; k++) {
        if (wv[k] != 0.0f) {
            const float4* s4 = (const float4*)(pts + ((size_t)b * NPTS + i0 + k) * DIM);
            float4* d4 = (float4*)(dstP + ((size_t)b * NPTS + p) * DIM);
            d4[0] = s4[0]; d4[1] = s4[1]; d4[2] = s4[2]; d4[3] = s4[3];
            dstW[b * NPTS + p] = wv[k];
            p++;
        }
    }
}

// ------------- pair kernel: 64x128 tile, 128 thr, 8x8 frag, pipelined -------
__global__ __launch_bounds__(NTHR, 4) void pair_kernel(float* out) {
    int b  = blockIdx.y;
    int Nv = g_cntA[b];
    int Mv = g_cntB[b];
    int active = (Nv + TN - 1) / TN;
    if (active < 1) active = 1;
    int bx = blockIdx.x;
    if (bx >= active) return;
    int n0 = bx * TN;

    __shared__ __align__(16) float As_t[16 * ASTR];
    __shared__ __align__(16) float Bs_t[16 * BSTR];
    __shared__ __align__(16) float asq[TN];
    __shared__ __align__(16) float bsq[TM];
    __shared__ float csh[2][4 * TM];
    __shared__ int   s_last;

    int tid  = threadIdx.x;
    int tx   = tid & 15;     // col group: cols tx*8 + c
    int ty   = tid >> 4;     // row group: rows ty*8 + r  (0..7)
    int lane = tid & 31;
    int wrp  = tid >> 5;     // 0..3
    int bro  = bpcol(tx * 8);
    int myc  = bpcol(tid);   // this thread's owned B column (physical)

    // ---- load A tile (64 rows x 16), k-transposed, + asq ----
    {
        int row = tid >> 1, half = tid & 1;
        int g = n0 + row;
        float4 v0 = make_float4(0.f, 0.f, 0.f, 0.f), v1 = v0;
        if (g < Nv) {
            const float4* p4 = (const float4*)(g_cA + ((size_t)b * NPTS + g) * DIM);
            v0 = p4[2 * half]; v1 = p4[2 * half + 1];
        }
        int k0 = 8 * half;
        As_t[(k0 + 0) * ASTR + row] = v0.x;
        As_t[(k0 + 1) * ASTR + row] = v0.y;
        As_t[(k0 + 2) * ASTR + row] = v0.z;
        As_t[(k0 + 3) * ASTR + row] = v0.w;
        As_t[(k0 + 4) * ASTR + row] = v1.x;
        As_t[(k0 + 5) * ASTR + row] = v1.y;
        As_t[(k0 + 6) * ASTR + row] = v1.z;
        As_t[(k0 + 7) * ASTR + row] = v1.w;
        float p = v0.x * v0.x + v0.y * v0.y + v0.z * v0.z + v0.w * v0.w
                + v1.x * v1.x + v1.y * v1.y + v1.z * v1.z + v1.w * v1.w;
        p += __shfl_xor_sync(0xFFFFFFFFu, p, 1);
        if (half == 0) asq[row] = (g < Nv) ? p : HUGEV;
    }

    float rowmin[8];
    #pragma unroll
    for (int r = 0; r < 8; r++) rowmin[r] = HUGEV;

    int mtiles = (Mv + TM - 1) / TM;

    // ---- prefetch B(0): this thread's column, 16 floats in regs ----
    float4 nb0, nb1, nb2, nb3;
    {
        float4 z = make_float4(0.f, 0.f, 0.f, 0.f);
        nb0 = nb1 = nb2 = nb3 = z;
        if (mtiles > 0 && tid < Mv) {
            const float4* p4 = (const float4*)(g_cB + ((size_t)b * NPTS + tid) * DIM);
            nb0 = p4[0]; nb1 = p4[1]; nb2 = p4[2]; nb3 = p4[3];
        }
    }

    for (int mt = 0; mt < mtiles; mt++) {
        int m0 = mt * TM;
        int par = mt & 1;

        // ---- STS B(mt) from regs (k-transposed, gapped cols) + bsq ----
        {
            Bs_t[ 0 * BSTR + myc] = nb0.x;
            Bs_t[ 1 * BSTR + myc] = nb0.y;
            Bs_t[ 2 * BSTR + myc] = nb0.z;
            Bs_t[ 3 * BSTR + myc] = nb0.w;
            Bs_t[ 4 * BSTR + myc] = nb1.x;
            Bs_t[ 5 * BSTR + myc] = nb1.y;
            Bs_t[ 6 * BSTR + myc] = nb1.z;
            Bs_t[ 7 * BSTR + myc] = nb1.w;
            Bs_t[ 8 * BSTR + myc] = nb2.x;
            Bs_t[ 9 * BSTR + myc] = nb2.y;
            Bs_t[10 * BSTR + myc] = nb2.z;
            Bs_t[11 * BSTR + myc] = nb2.w;
            Bs_t[12 * BSTR + myc] = nb3.x;
            Bs_t[13 * BSTR + myc] = nb3.y;
            Bs_t[14 * BSTR + myc] = nb3.z;
            Bs_t[15 * BSTR + myc] = nb3.w;
            float p = nb0.x*nb0.x + nb0.y*nb0.y + nb0.z*nb0.z + nb0.w*nb0.w
                    + nb1.x*nb1.x + nb1.y*nb1.y + nb1.z*nb1.z + nb1.w*nb1.w
                    + nb2.x*nb2.x + nb2.y*nb2.y + nb2.z*nb2.z + nb2.w*nb2.w
                    + nb3.x*nb3.x + nb3.y*nb3.y + nb3.z*nb3.z + nb3.w*nb3.w;
            bsq[tid] = (m0 + tid < Mv) ? p : HUGEV;
        }
        __syncthreads();   // Bs/bsq ready (A stores also covered on mt==0)

        // ---- prefetch B(mt+1) ----
        if (mt + 1 < mtiles) {
            int g = m0 + TM + tid;
            float4 z = make_float4(0.f, 0.f, 0.f, 0.f);
            nb0 = nb1 = nb2 = nb3 = z;
            if (g < Mv) {
                const float4* p4 = (const float4*)(g_cB + ((size_t)b * NPTS + g) * DIM);
                nb0 = p4[0]; nb1 = p4[1]; nb2 = p4[2]; nb3 = p4[3];
            }
        }

        // ---- mainloop: acc[p][c] = rows(2p,2p+1) x col c, f32x2 over rows
        ull acc[4][8];
        #pragma unroll
        for (int p = 0; p < 4; p++)
            #pragma unroll
            for (int c = 0; c < 8; c++) acc[p][c] = 0ull;

        #pragma unroll
        for (int k = 0; k < 16; k++) {
            const float* arow = As_t + k * ASTR + ty * 8;
            ulonglong2 A0 = *(const ulonglong2*)(arow);
            ulonglong2 A1 = *(const ulonglong2*)(arow + 4);
            const float* brow = Bs_t + k * BSTR + bro;
            float4 B0 = *(const float4*)(brow);
            float4 B1 = *(const float4*)(brow + 4);
            ull a2[4] = {A0.x, A0.y, A1.x, A1.y};
            float bs[8] = {B0.x, B0.y, B0.z, B0.w, B1.x, B1.y, B1.z, B1.w};
            #pragma unroll
            for (int c = 0; c < 8; c++) {
                ull bb = bcast2(bs[c]);
                #pragma unroll
                for (int p = 0; p < 4; p++) fma2(acc[p][c], a2[p], bb);
            }
        }

        // ---- epilogue: d2 = asq + bsq - 2*dot (packed), row/col mins ----
        ulonglong2 q0 = *(const ulonglong2*)(asq + ty * 8);
        ulonglong2 q1 = *(const ulonglong2*)(asq + ty * 8 + 4);
        ull aq2[4] = {q0.x, q0.y, q1.x, q1.y};
        const ull NEG2 = 0xC0000000C0000000ull;   // (-2.0f, -2.0f)
        float cm[8];
        #pragma unroll
        for (int c = 0; c < 8; c++) cm[c] = HUGEV;
        #pragma unroll
        for (int c = 0; c < 8; c++) {
            ull bb = bcast2(bsq[tx * 8 + c]);
            #pragma unroll
            for (int p = 0; p < 4; p++) {
                ull s2 = add2(aq2[p], bb);
                ull d2 = fma2v(NEG2, acc[p][c], s2);
                float lo, hi;
                unpack2(d2, lo, hi);
                rowmin[2 * p]     = fminf(rowmin[2 * p], lo);
                rowmin[2 * p + 1] = fminf(rowmin[2 * p + 1], hi);
                cm[c] = fminf(cm[c], fminf(lo, hi));
            }
        }

        // ---- col-min: shfl across ty pair, stage per-warp, atomicMin ----
        #pragma unroll
        for (int c = 0; c < 8; c++) {
            float v = fmaxf(cm[c], 0.0f);   // clamp -> int-ordered atomicMin
            v = fminf(v, __shfl_xor_sync(0xFFFFFFFFu, v, 16));
            if (lane < 16) csh[par][wrp * TM + tx * 8 + c] = v;
        }
        __syncthreads();   // csh ready; Bs consumers done (next STS safe)
        {
            float v =             csh[par][0 * TM + tid];
            v = fminf(v,          csh[par][1 * TM + tid]);
            v = fminf(v,          csh[par][2 * TM + tid]);
            v = fminf(v,          csh[par][3 * TM + tid]);
            if (m0 + tid < Mv)
                atomicMin(&g_colmin[b * NPTS + m0 + tid], __float_as_int(v));
        }
    }

    // ---- row-min reduction over tx lanes (xor 1,2,4,8) ----
    #pragma unroll
    for (int r = 0; r < 8; r++) {
        float v = rowmin[r];
        v = fminf(v, __shfl_xor_sync(0xFFFFFFFFu, v, 1));
        v = fminf(v, __shfl_xor_sync(0xFFFFFFFFu, v, 2));
        v = fminf(v, __shfl_xor_sync(0xFFFFFFFFu, v, 4));
        v = fminf(v, __shfl_xor_sync(0xFFFFFFFFu, v, 8));
        rowmin[r] = v;
    }
    if (tx == 0) {
        float contrib = 0.0f;
        #pragma unroll
        for (int r = 0; r < 8; r++) {
            int g = n0 + ty * 8 + r;
            if (g < Nv) {
                float rv = rowmin[r];
                float val = (rv >= 1e29f) ? BIG2 : fmaxf(rv, 0.0f);
                contrib += val * g_wA[b * NPTS + g];
            }
        }
        atomicAdd(&out[b], contrib);
    }

    // ---- last block of this batch finalizes the column mins ----
    __threadfence();
    __syncthreads();
    if (tid == 0)
        s_last = (atomicAdd(&g_done[b], 1) == active - 1) ? 1 : 0;
    __syncthreads();
    if (s_last) {
        float s = 0.0f;
        for (int m = tid; m < Mv; m += NTHR) {
            float v = __int_as_float(__ldcg(&g_colmin[b * NPTS + m]));
            v = (v >= 1e29f) ? BIG2 : v;
            s += v * g_wB[b * NPTS + m];
        }
        #pragma unroll
        for (int d = 16; d > 0; d >>= 1)
            s += __shfl_xor_sync(0xFFFFFFFFu, s, d);
        if (lane == 0) atomicAdd(&out[b], s);
    }
}

// ---------------- launch ----------------
extern "C" void kernel_launch(void* const* d_in, const int* in_sizes, int n_in,
                              void* d_out, int out_size) {
    const float* ow = (const float*)d_in[0];  // [B, N]
    const float* op = (const float*)d_in[1];  // [B, N, D]
    const float* tw = (const float*)d_in[2];  // [B, M]
    const float* tp = (const float*)d_in[3];  // [B, M, D]
    float* out = (float*)d_out;               // [B]

    setup_kernel<<<2 * BATCH, 256>>>(ow, op, tw, tp, out);
    dim3 grid(NPTS / TN, BATCH);
    pair_kernel<<<grid, NTHR>>>(out);
}

// round 8
// speedup vs baseline: 1.0032x; 1.0032x over previous
#include <cuda_runtime.h>
#include <cstdint>

#define BATCH 32
#define NPTS  2048
#define DIM   16
#define TN    64
#define TM    128
#define NTHR  128
#define GRIDX 18             // one clean wave: 18*32 = 576 blocks (~592 slots)
#define NTILE (NPTS / TN)    // 32 logical n-tiles, strided by GRIDX
#define ASTR  72             // A transposed row stride (floats)
#define BSTR  144            // B transposed row stride (floats), gapped
#define BIG2  1.0e16f
#define HUGEV 1.0e30f

typedef unsigned long long ull;

// physical column for Bs_t: 4-float gap every 32 columns (bank de-conflict)
__device__ __forceinline__ int bpcol(int col) { return col + ((col >> 5) << 2); }

// ---------------- scratch (no allocs allowed) ----------------
__device__ float g_cA[BATCH * NPTS * DIM];
__device__ float g_cB[BATCH * NPTS * DIM];
__device__ float g_wA[BATCH * NPTS];
__device__ float g_wB[BATCH * NPTS];
__device__ int   g_cntA[BATCH];
__device__ int   g_cntB[BATCH];
__device__ int   g_colmin[BATCH * NPTS];   // float-as-int (nonneg), +inf init
__device__ int   g_done[BATCH];

// ---------------- packed f32x2 helpers ----------------
__device__ __forceinline__ void fma2(ull& d, ull a, ull b) {
    asm("fma.rn.f32x2 %0, %1, %2, %0;" : "+l"(d) : "l"(a), "l"(b));
}
__device__ __forceinline__ ull fma2v(ull a, ull b, ull c) {
    ull d; asm("fma.rn.f32x2 %0, %1, %2, %3;" : "=l"(d) : "l"(a), "l"(b), "l"(c));
    return d;
}
__device__ __forceinline__ ull add2(ull a, ull b) {
    ull d; asm("add.rn.f32x2 %0, %1, %2;" : "=l"(d) : "l"(a), "l"(b));
    return d;
}
__device__ __forceinline__ ull bcast2(float x) {
    ull d; asm("mov.b64 %0, {%1, %1};" : "=l"(d) : "f"(x));
    return d;
}
__device__ __forceinline__ void unpack2(ull v, float& lo, float& hi) {
    asm("mov.b64 {%0, %1}, %2;" : "=f"(lo), "=f"(hi) : "l"(v));
}

// ---------------- setup: init + prefix-scan compaction ----------------
__global__ __launch_bounds__(256) void setup_kernel(
    const float* __restrict__ ow, const float* __restrict__ op,
    const float* __restrict__ tw, const float* __restrict__ tp,
    float* out) {
    int blk = blockIdx.x;              // 64 blocks: (b, sel)
    int b   = blk >> 1;
    int sel = blk & 1;
    int tid = threadIdx.x, lane = tid & 31, wrp = tid >> 5;

    int base = blk * 1024;
    for (int i = tid; i < 1024; i += 256) g_colmin[base + i] = 0x7F800000;
    if (sel == 0 && tid == 0) { out[b] = 0.0f; g_done[b] = 0; }

    const float* w   = sel ? tw : ow;
    const float* pts = sel ? tp : op;
    float* dstP = sel ? g_cB : g_cA;
    float* dstW = sel ? g_wB : g_wA;
    int*   cnt  = sel ? g_cntB : g_cntA;

    int i0 = tid * 8;
    float wv[8];
    int c = 0;
    #pragma unroll
    for (int k = 0; k < 8; k++) {
        wv[k] = w[b * NPTS + i0 + k];
        c += (wv[k] != 0.0f);
    }
    int incl = c;
    #pragma unroll
    for (int d = 1; d < 32; d <<= 1) {
        int n = __shfl_up_sync(0xFFFFFFFFu, incl, d);
        if (lane >= d) incl += n;
    }
    __shared__ int wtot[8], wbase[8];
    if (lane == 31) wtot[wrp] = incl;
    __syncthreads();
    if (tid == 0) {
        int s = 0;
        #pragma unroll
        for (int wI = 0; wI < 8; wI++) { wbase[wI] = s; s += wtot[wI]; }
        cnt[b] = s;
    }
    __syncthreads();
    int p = wbase[wrp] + incl - c;
    #pragma unroll
    for (int k = 0; k < 8; k++) {
        if (wv[k] != 0.0f) {
            const float4* s4 = (const float4*)(pts + ((size_t)b * NPTS + i0 + k) * DIM);
            float4* d4 = (float4*)(dstP + ((size_t)b * NPTS + p) * DIM);
            d4[0] = s4[0]; d4[1] = s4[1]; d4[2] = s4[2]; d4[3] = s4[3];
            dstW[b * NPTS + p] = wv[k];
            p++;
        }
    }
}

// ------- pair kernel: 64x128 tile, 128 thr, 8x8 frag, strided n-tiles ------
__global__ __launch_bounds__(NTHR, 4) void pair_kernel(float* out) {
    int b  = blockIdx.y;
    int Nv = g_cntA[b];
    int Mv = g_cntB[b];
    int bx = blockIdx.x;

    __shared__ __align__(16) float As_t[16 * ASTR];
    __shared__ __align__(16) float Bs_t[16 * BSTR];
    __shared__ __align__(16) float asq[TN];
    __shared__ __align__(16) float bsq[TM];
    __shared__ float csh[2][4 * TM];
    __shared__ int   s_last;

    int tid  = threadIdx.x;
    int tx   = tid & 15;     // col group: cols tx*8 + c
    int ty   = tid >> 4;     // row group: rows ty*8 + r
    int lane = tid & 31;
    int wrp  = tid >> 5;
    int bro  = bpcol(tx * 8);
    int myc  = bpcol(tid);   // this thread's owned B column (physical)
    int mtiles = (Mv + TM - 1) / TM;

    // strided n-tile loop: t covers {bx, bx+18} (2nd tile rarely active)
    for (int t = bx; t < NTILE; t += GRIDX) {
        int n0 = t * TN;
        if (n0 >= Nv) break;

        __syncthreads();   // protect As_t/asq reuse across t-iterations

        // ---- load A tile (64 rows x 16), k-transposed, + asq ----
        {
            int row = tid >> 1, half = tid & 1;
            int g = n0 + row;
            float4 v0 = make_float4(0.f, 0.f, 0.f, 0.f), v1 = v0;
            if (g < Nv) {
                const float4* p4 = (const float4*)(g_cA + ((size_t)b * NPTS + g) * DIM);
                v0 = p4[2 * half]; v1 = p4[2 * half + 1];
            }
            int k0 = 8 * half;
            As_t[(k0 + 0) * ASTR + row] = v0.x;
            As_t[(k0 + 1) * ASTR + row] = v0.y;
            As_t[(k0 + 2) * ASTR + row] = v0.z;
            As_t[(k0 + 3) * ASTR + row] = v0.w;
            As_t[(k0 + 4) * ASTR + row] = v1.x;
            As_t[(k0 + 5) * ASTR + row] = v1.y;
            As_t[(k0 + 6) * ASTR + row] = v1.z;
            As_t[(k0 + 7) * ASTR + row] = v1.w;
            float p = v0.x * v0.x + v0.y * v0.y + v0.z * v0.z + v0.w * v0.w
                    + v1.x * v1.x + v1.y * v1.y + v1.z * v1.z + v1.w * v1.w;
            p += __shfl_xor_sync(0xFFFFFFFFu, p, 1);
            if (half == 0) asq[row] = (g < Nv) ? p : HUGEV;
        }

        float rowmin[8];
        #pragma unroll
        for (int r = 0; r < 8; r++) rowmin[r] = HUGEV;

        // ---- prefetch B(0): this thread's column, 16 floats in regs ----
        float4 nb0, nb1, nb2, nb3;
        {
            float4 z = make_float4(0.f, 0.f, 0.f, 0.f);
            nb0 = nb1 = nb2 = nb3 = z;
            if (mtiles > 0 && tid < Mv) {
                const float4* p4 = (const float4*)(g_cB + ((size_t)b * NPTS + tid) * DIM);
                nb0 = p4[0]; nb1 = p4[1]; nb2 = p4[2]; nb3 = p4[3];
            }
        }

        for (int mt = 0; mt < mtiles; mt++) {
            int m0 = mt * TM;
            int par = mt & 1;

            // ---- STS B(mt) from regs (k-transposed, gapped cols) + bsq ----
            {
                Bs_t[ 0 * BSTR + myc] = nb0.x;
                Bs_t[ 1 * BSTR + myc] = nb0.y;
                Bs_t[ 2 * BSTR + myc] = nb0.z;
                Bs_t[ 3 * BSTR + myc] = nb0.w;
                Bs_t[ 4 * BSTR + myc] = nb1.x;
                Bs_t[ 5 * BSTR + myc] = nb1.y;
                Bs_t[ 6 * BSTR + myc] = nb1.z;
                Bs_t[ 7 * BSTR + myc] = nb1.w;
                Bs_t[ 8 * BSTR + myc] = nb2.x;
                Bs_t[ 9 * BSTR + myc] = nb2.y;
                Bs_t[10 * BSTR + myc] = nb2.z;
                Bs_t[11 * BSTR + myc] = nb2.w;
                Bs_t[12 * BSTR + myc] = nb3.x;
                Bs_t[13 * BSTR + myc] = nb3.y;
                Bs_t[14 * BSTR + myc] = nb3.z;
                Bs_t[15 * BSTR + myc] = nb3.w;
                float p = nb0.x*nb0.x + nb0.y*nb0.y + nb0.z*nb0.z + nb0.w*nb0.w
                        + nb1.x*nb1.x + nb1.y*nb1.y + nb1.z*nb1.z + nb1.w*nb1.w
                        + nb2.x*nb2.x + nb2.y*nb2.y + nb2.z*nb2.z + nb2.w*nb2.w
                        + nb3.x*nb3.x + nb3.y*nb3.y + nb3.z*nb3.z + nb3.w*nb3.w;
                bsq[tid] = (m0 + tid < Mv) ? p : HUGEV;
            }
            __syncthreads();   // Bs/bsq ready (A stores also covered on mt==0)

            // ---- prefetch B(mt+1) ----
            if (mt + 1 < mtiles) {
                int g = m0 + TM + tid;
                float4 z = make_float4(0.f, 0.f, 0.f, 0.f);
                nb0 = nb1 = nb2 = nb3 = z;
                if (g < Mv) {
                    const float4* p4 = (const float4*)(g_cB + ((size_t)b * NPTS + g) * DIM);
                    nb0 = p4[0]; nb1 = p4[1]; nb2 = p4[2]; nb3 = p4[3];
                }
            }

            // ---- mainloop: acc[p][c] = rows(2p,2p+1) x col c, f32x2 ----
            ull acc[4][8];
            #pragma unroll
            for (int p = 0; p < 4; p++)
                #pragma unroll
                for (int c = 0; c < 8; c++) acc[p][c] = 0ull;

            #pragma unroll
            for (int k = 0; k < 16; k++) {
                const float* arow = As_t + k * ASTR + ty * 8;
                ulonglong2 A0 = *(const ulonglong2*)(arow);
                ulonglong2 A1 = *(const ulonglong2*)(arow + 4);
                const float* brow = Bs_t + k * BSTR + bro;
                float4 B0 = *(const float4*)(brow);
                float4 B1 = *(const float4*)(brow + 4);
                ull a2[4] = {A0.x, A0.y, A1.x, A1.y};
                float bs[8] = {B0.x, B0.y, B0.z, B0.w, B1.x, B1.y, B1.z, B1.w};
                #pragma unroll
                for (int c = 0; c < 8; c++) {
                    ull bb = bcast2(bs[c]);
                    #pragma unroll
                    for (int p = 0; p < 4; p++) fma2(acc[p][c], a2[p], bb);
                }
            }

            // ---- epilogue: d2 = asq + bsq - 2*dot (packed), scalar mins ----
            ulonglong2 q0 = *(const ulonglong2*)(asq + ty * 8);
            ulonglong2 q1 = *(const ulonglong2*)(asq + ty * 8 + 4);
            ull aq2[4] = {q0.x, q0.y, q1.x, q1.y};
            const ull NEG2 = 0xC0000000C0000000ull;   // (-2.0f, -2.0f)
            float cm[8];
            #pragma unroll
            for (int c = 0; c < 8; c++) cm[c] = HUGEV;
            #pragma unroll
            for (int c = 0; c < 8; c++) {
                ull bb = bcast2(bsq[tx * 8 + c]);
                #pragma unroll
                for (int p = 0; p < 4; p++) {
                    ull d2 = fma2v(NEG2, acc[p][c], add2(aq2[p], bb));
                    float lo, hi;
                    unpack2(d2, lo, hi);
                    rowmin[2 * p]     = fminf(rowmin[2 * p], lo);
                    rowmin[2 * p + 1] = fminf(rowmin[2 * p + 1], hi);
                    cm[c] = fminf(cm[c], fminf(lo, hi));
                }
            }

            // ---- col-min: shfl across ty pair, stage per-warp, atomicMin --
            #pragma unroll
            for (int c = 0; c < 8; c++) {
                float v = fmaxf(cm[c], 0.0f);   // clamp -> int-ordered atomicMin
                v = fminf(v, __shfl_xor_sync(0xFFFFFFFFu, v, 16));
                if (lane < 16) csh[par][wrp * TM + tx * 8 + c] = v;
            }
            __syncthreads();   // csh ready; Bs consumers done (next STS safe)
            {
                float v =    csh[par][0 * TM + tid];
                v = fminf(v, csh[par][1 * TM + tid]);
                v = fminf(v, csh[par][2 * TM + tid]);
                v = fminf(v, csh[par][3 * TM + tid]);
                if (m0 + tid < Mv)
                    atomicMin(&g_colmin[b * NPTS + m0 + tid], __float_as_int(v));
            }
        }

        // ---- row-min reduction over tx lanes (xor 1,2,4,8) ----
        #pragma unroll
        for (int r = 0; r < 8; r++) {
            float v = rowmin[r];
            v = fminf(v, __shfl_xor_sync(0xFFFFFFFFu, v, 1));
            v = fminf(v, __shfl_xor_sync(0xFFFFFFFFu, v, 2));
            v = fminf(v, __shfl_xor_sync(0xFFFFFFFFu, v, 4));
            v = fminf(v, __shfl_xor_sync(0xFFFFFFFFu, v, 8));
            rowmin[r] = v;
        }
        if (tx == 0) {
            float contrib = 0.0f;
            #pragma unroll
            for (int r = 0; r < 8; r++) {
                int g = n0 + ty * 8 + r;
                if (g < Nv) {
                    float rv = rowmin[r];
                    float val = (rv >= 1e29f) ? BIG2 : fmaxf(rv, 0.0f);
                    contrib += val * g_wA[b * NPTS + g];
                }
            }
            atomicAdd(&out[b], contrib);
        }
    }

    // ---- every block arrives once; last of GRIDX finalizes col mins ----
    __threadfence();
    __syncthreads();
    if (tid == 0)
        s_last = (atomicAdd(&g_done[b], 1) == GRIDX - 1) ? 1 : 0;
    __syncthreads();
    if (s_last) {
        float s = 0.0f;
        for (int m = tid; m < Mv; m += NTHR) {
            float v = __int_as_float(__ldcg(&g_colmin[b * NPTS + m]));
            v = (v >= 1e29f) ? BIG2 : v;
            s += v * g_wB[b * NPTS + m];
        }
        #pragma unroll
        for (int d = 16; d > 0; d >>= 1)
            s += __shfl_xor_sync(0xFFFFFFFFu, s, d);
        if (lane == 0) atomicAdd(&out[b], s);
    }
}

// ---------------- launch ----------------
extern "C" void kernel_launch(void* const* d_in, const int* in_sizes, int n_in,
                              void* d_out, int out_size) {
    const float* ow = (const float*)d_in[0];  // [B, N]
    const float* op = (const float*)d_in[1];  // [B, N, D]
    const float* tw = (const float*)d_in[2];  // [B, M]
    const float* tp = (const float*)d_in[3];  // [B, M, D]
    float* out = (float*)d_out;               // [B]

    setup_kernel<<<2 * BATCH, 256>>>(ow, op, tw, tp, out);
    dim3 grid(GRIDX, BATCH);
    pair_kernel<<<grid, NTHR>>>(out);
}